// round 9
// baseline (speedup 1.0000x reference)
#include <cuda_runtime.h>
#include <math.h>
#include <stdint.h>

#define BB     2
#define NN     4096
#define QDIM   512
#define HEADS  8
#define DH     64
#define INNER  512
#define ROWS   (BB * NN)          // 8192
// 64^-0.5 * log2(e): S computed in log2 domain, P = ex2(S)
#define SCALE_L2E  (0.125f * 1.4426950408889634f)

#define QSTR   72      // Qs/Ks row stride: conflict-free paired (LDS.64) k-loads
#define VSTR   68      // Vs row stride: conflict-free scalar column loads
#define NT     (NN / 64)

// Scratch (device globals: allocation-free per harness rules)
__device__ float g_Q[(size_t)ROWS * INNER];
__device__ float g_K[(size_t)ROWS * INNER];
__device__ float g_V[(size_t)ROWS * INNER];
__device__ float g_O[(size_t)ROWS * INNER];

// ---------------------------------------------------------------------------
// helpers
// ---------------------------------------------------------------------------
__device__ __forceinline__ uint32_t f2tf(float x) {
    uint32_t u;
    asm("cvt.rna.tf32.f32 %0, %1;" : "=r"(u) : "f"(x));
    return u;
}

__device__ __forceinline__ float ex2(float x) {
    float y;
    asm("ex2.approx.ftz.f32 %0, %1;" : "=f"(y) : "f"(x));
    return y;
}

__device__ __forceinline__ uint32_t fu(float x) { return __float_as_uint(x); }
__device__ __forceinline__ float uf(uint32_t x) { return __uint_as_float(x); }

__device__ __forceinline__ void mma_tf32(float d[4], uint32_t a0, uint32_t a1,
                                         uint32_t a2, uint32_t a3,
                                         uint32_t b0, uint32_t b1) {
    asm("mma.sync.aligned.m16n8k8.row.col.f32.tf32.tf32.f32 "
        "{%0,%1,%2,%3},{%4,%5,%6,%7},{%8,%9},{%0,%1,%2,%3};"
        : "+f"(d[0]), "+f"(d[1]), "+f"(d[2]), "+f"(d[3])
        : "r"(a0), "r"(a1), "r"(a2), "r"(a3), "r"(b0), "r"(b1));
}

__device__ __forceinline__ void split_tf(float x, uint32_t& hi, uint32_t& lo) {
    hi = f2tf(x);
    lo = f2tf(x - __uint_as_float(hi));
}

__device__ __forceinline__ void split4(float4 v, float4& h, float4& l) {
    uint32_t hx, lx, hy, ly, hz, lz, hw, lw;
    split_tf(v.x, hx, lx);
    split_tf(v.y, hy, ly);
    split_tf(v.z, hz, lz);
    split_tf(v.w, hw, lw);
    h = make_float4(uf(hx), uf(hy), uf(hz), uf(hw));
    l = make_float4(uf(lx), uf(ly), uf(lz), uf(lw));
}

__device__ __forceinline__ void cp16(uint32_t dst, const void* src) {
    asm volatile("cp.async.cg.shared.global [%0], [%1], 16;" :: "r"(dst), "l"(src));
}

// ---------------------------------------------------------------------------
// GEMM (3xTF32 split, fp32-accurate): C[.,512] = A[M,512] @ B[512,512] (+bias)
// Block 128x128, k-step 32, 8 warps (2m x 4n), warp tile 64x32.
// Register-staged double buffer: LDG -> split ONCE -> STS hi/lo arrays.
// Inner loop: pure LDS.64 / conflict-free scalar loads + 3 mmas per tile pair.
// ---------------------------------------------------------------------------
#define ASTR 40
#define BSTR 132
#define GN   512
#define GKT  16

__device__ __forceinline__ void ldg_tile(const float* __restrict__ A,
                                         const float* __restrict__ Bm,
                                         int m0, int n0, int kt,
                                         float4 aR[4], float4 bR[4]) {
    const int tid = threadIdx.x;
#pragma unroll
    for (int i = 0; i < 4; i++) {
        int idx = tid + i * 256;
        int r = idx >> 3, c8 = idx & 7;
        aR[i] = *(const float4*)&A[(size_t)(m0 + r) * 512 + kt * 32 + c8 * 4];
    }
#pragma unroll
    for (int i = 0; i < 4; i++) {
        int idx = tid + i * 256;
        int r = idx >> 5, c4 = idx & 31;
        bR[i] = *(const float4*)&Bm[(size_t)(kt * 32 + r) * GN + n0 + c4 * 4];
    }
}

__device__ __forceinline__ void sts_tile(float* Ahi, float* Alo, float* Bhi,
                                         float* Blo, int buf,
                                         const float4 aR[4], const float4 bR[4]) {
    const int tid = threadIdx.x;
    float* ah = Ahi + buf * 128 * ASTR;
    float* al = Alo + buf * 128 * ASTR;
    float* bh = Bhi + buf * 32 * BSTR;
    float* bl = Blo + buf * 32 * BSTR;
#pragma unroll
    for (int i = 0; i < 4; i++) {
        int idx = tid + i * 256;
        int r = idx >> 3, c8 = idx & 7;
        float4 h, l;
        split4(aR[i], h, l);
        *(float4*)&ah[r * ASTR + c8 * 4] = h;
        *(float4*)&al[r * ASTR + c8 * 4] = l;
    }
#pragma unroll
    for (int i = 0; i < 4; i++) {
        int idx = tid + i * 256;
        int r = idx >> 5, c4 = idx & 31;
        float4 h, l;
        split4(bR[i], h, l);
        *(float4*)&bh[r * BSTR + c4 * 4] = h;
        *(float4*)&bl[r * BSTR + c4 * 4] = l;
    }
}

__device__ __forceinline__ void gemm_core(const float* __restrict__ A,
                                          const float* __restrict__ Bm,
                                          const float* __restrict__ bias,
                                          float* __restrict__ C,
                                          int m0, int n0, float* smg,
                                          bool has_bias) {
    float* Ahi = smg;                       // [2][128][ASTR]
    float* Alo = Ahi + 2 * 128 * ASTR;
    float* Bhi = Alo + 2 * 128 * ASTR;      // [2][32][BSTR]
    float* Blo = Bhi + 2 * 32 * BSTR;

    const int tid = threadIdx.x;
    const int lane = tid & 31, wid = tid >> 5;
    const int t = lane & 3, g = lane >> 2;
    const int wm = wid >> 2, wn = wid & 3;

    float4 aR[4], bR[4];
    ldg_tile(A, Bm, m0, n0, 0, aR, bR);
    sts_tile(Ahi, Alo, Bhi, Blo, 0, aR, bR);
    ldg_tile(A, Bm, m0, n0, 1, aR, bR);
    __syncthreads();

    float acc[4][4][4];
#pragma unroll
    for (int i = 0; i < 4; i++)
#pragma unroll
        for (int j = 0; j < 4; j++)
#pragma unroll
            for (int e = 0; e < 4; e++) acc[i][j][e] = 0.f;

    for (int kt = 0; kt < GKT; kt++) {
        const float* ah = Ahi + (kt & 1) * 128 * ASTR;
        const float* al = Alo + (kt & 1) * 128 * ASTR;
        const float* bh = Bhi + (kt & 1) * 32 * BSTR;
        const float* bl = Blo + (kt & 1) * 32 * BSTR;

#pragma unroll
        for (int kk = 0; kk < 32; kk += 8) {
            uint32_t Ah[4][4], Al[4][4];
#pragma unroll
            for (int mt = 0; mt < 4; mt++) {
                int mb = wm * 64 + mt * 16;
                float2 h0 = *(const float2*)&ah[(mb + g) * ASTR + kk + 2 * t];
                float2 h1 = *(const float2*)&ah[(mb + g + 8) * ASTR + kk + 2 * t];
                float2 l0 = *(const float2*)&al[(mb + g) * ASTR + kk + 2 * t];
                float2 l1 = *(const float2*)&al[(mb + g + 8) * ASTR + kk + 2 * t];
                Ah[mt][0] = fu(h0.x); Ah[mt][1] = fu(h1.x);
                Ah[mt][2] = fu(h0.y); Ah[mt][3] = fu(h1.y);
                Al[mt][0] = fu(l0.x); Al[mt][1] = fu(l1.x);
                Al[mt][2] = fu(l0.y); Al[mt][3] = fu(l1.y);
            }
            uint32_t Bh[4][2], Bl[4][2];
#pragma unroll
            for (int nt = 0; nt < 4; nt++) {
                int nb = wn * 32 + nt * 8;
                Bh[nt][0] = fu(bh[(kk + 2 * t) * BSTR + nb + g]);
                Bh[nt][1] = fu(bh[(kk + 2 * t + 1) * BSTR + nb + g]);
                Bl[nt][0] = fu(bl[(kk + 2 * t) * BSTR + nb + g]);
                Bl[nt][1] = fu(bl[(kk + 2 * t + 1) * BSTR + nb + g]);
            }
#pragma unroll
            for (int mt = 0; mt < 4; mt++)
#pragma unroll
                for (int nt = 0; nt < 4; nt++) {
                    mma_tf32(acc[mt][nt], Ah[mt][0], Ah[mt][1], Ah[mt][2], Ah[mt][3],
                             Bh[nt][0], Bh[nt][1]);
                    mma_tf32(acc[mt][nt], Ah[mt][0], Ah[mt][1], Ah[mt][2], Ah[mt][3],
                             Bl[nt][0], Bl[nt][1]);
                    mma_tf32(acc[mt][nt], Al[mt][0], Al[mt][1], Al[mt][2], Al[mt][3],
                             Bh[nt][0], Bh[nt][1]);
                }
        }

        if (kt + 1 < GKT) {
            __syncthreads();  // all warps done reading buf (kt+1)&1
            sts_tile(Ahi, Alo, Bhi, Blo, (kt + 1) & 1, aR, bR);
            if (kt + 2 < GKT) ldg_tile(A, Bm, m0, n0, kt + 2, aR, bR);
            __syncthreads();  // tile kt+1 visible to all
        }
    }

    // epilogue
#pragma unroll
    for (int mt = 0; mt < 4; mt++) {
#pragma unroll
        for (int nt = 0; nt < 4; nt++) {
            int r = m0 + wm * 64 + mt * 16 + g;
            int c = n0 + wn * 32 + nt * 8 + 2 * t;
            float b0 = has_bias ? bias[c] : 0.f;
            float b1 = has_bias ? bias[c + 1] : 0.f;
            float2 v0 = make_float2(acc[mt][nt][0] + b0, acc[mt][nt][1] + b1);
            float2 v1 = make_float2(acc[mt][nt][2] + b0, acc[mt][nt][3] + b1);
            *(float2*)&C[(size_t)r * GN + c] = v0;
            *(float2*)&C[(size_t)(r + 8) * GN + c] = v1;
        }
    }
}

// Fused QKV projection: grid.x = 12 (3 matrices x 4 n-blocks)
__global__ __launch_bounds__(256, 1) void gemm_qkv(const float* __restrict__ x,
                                                   const float* __restrict__ Wq,
                                                   const float* __restrict__ Wk,
                                                   const float* __restrict__ Wv,
                                                   float* __restrict__ Qd,
                                                   float* __restrict__ Kd,
                                                   float* __restrict__ Vd) {
    extern __shared__ float smg[];
    const int sel = blockIdx.x >> 2;
    const float* B = (sel == 0) ? Wq : (sel == 1) ? Wk : Wv;
    float* C = (sel == 0) ? Qd : (sel == 1) ? Kd : Vd;
    gemm_core(x, B, nullptr, C, blockIdx.y * 128, (blockIdx.x & 3) * 128, smg, false);
}

// Output projection (with bias): grid.x = 4
__global__ __launch_bounds__(256, 1) void gemm_out(const float* __restrict__ A,
                                                   const float* __restrict__ Wo,
                                                   const float* __restrict__ bo,
                                                   float* __restrict__ out) {
    extern __shared__ float smg[];
    gemm_core(A, Wo, bo, out, blockIdx.y * 128, blockIdx.x * 128, smg, true);
}

// ---------------------------------------------------------------------------
// Flash attention v5 (unchanged from round-8 baseline): warp-row ownership;
// K+V double-buffered cp.async (depth 2); LDS.64 S-phase fragment loads
// (k-slot perm, stride 72); conflict-free scalar PV loads (stride 68).
// 2 CTAs/SM. Softmax in log2 domain (ex2), no max-subtraction.
// ---------------------------------------------------------------------------
__global__ __launch_bounds__(256, 2) void attn_tc5() {
    extern __shared__ float sm[];
    float* Qs = sm;                                   // [128][QSTR]
    float* Ks = sm + 128 * QSTR;                      // [2][64][QSTR]
    float* Vs = sm + 128 * QSTR + 2 * 64 * QSTR;      // [2][64][VSTR]

    const int tid = threadIdx.x;
    const int lane = tid & 31, wid = tid >> 5;
    const int t = lane & 3, g = lane >> 2;
    const int b = blockIdx.z, h = blockIdx.y;
    const int r0 = blockIdx.x * 128;
    const int mb = wid * 16;

    const float* Qp = g_Q + ((size_t)b * NN + r0) * INNER + h * DH;
    const float* Kp = g_K + ((size_t)b * NN) * INNER + h * DH;
    const float* Vp = g_V + ((size_t)b * NN) * INNER + h * DH;

    const uint32_t ks_u = (uint32_t)__cvta_generic_to_shared(Ks);
    const uint32_t vs_u = (uint32_t)__cvta_generic_to_shared(Vs);
    const int lr = tid >> 4, lc = tid & 15;

    // --- pre-issue KV tiles 0,1 (one commit group per tile) ---
#pragma unroll
    for (int pre = 0; pre < 2; pre++) {
#pragma unroll
        for (int i = 0; i < 4; i++) {
            int rr = lr + i * 16;
            cp16(ks_u + (uint32_t)(pre * 64 * QSTR + rr * QSTR + lc * 4) * 4,
                 Kp + (size_t)(pre * 64 + rr) * INNER + lc * 4);
            cp16(vs_u + (uint32_t)(pre * 64 * VSTR + rr * VSTR + lc * 4) * 4,
                 Vp + (size_t)(pre * 64 + rr) * INNER + lc * 4);
        }
        asm volatile("cp.async.commit_group;");
    }

    // --- stage Q (fold scale*log2e, single RNA tf32 round) ---
#pragma unroll
    for (int i = 0; i < 8; i++) {
        int idx = tid + i * 256;
        int r = idx >> 4, c4 = idx & 15;
        float4 v = *(const float4*)&Qp[(size_t)r * INNER + c4 * 4];
        float4 w;
        w.x = uf(f2tf(v.x * SCALE_L2E));
        w.y = uf(f2tf(v.y * SCALE_L2E));
        w.z = uf(f2tf(v.z * SCALE_L2E));
        w.w = uf(f2tf(v.w * SCALE_L2E));
        *(float4*)&Qs[r * QSTR + c4 * 4] = w;
    }

    float o[8][4];
#pragma unroll
    for (int nt = 0; nt < 8; nt++)
#pragma unroll
        for (int e = 0; e < 4; e++) o[nt][e] = 0.f;
    float l0 = 0.f, l1 = 0.f;

    for (int it = 0; it < NT; ++it) {
        if (it + 1 < NT)
            asm volatile("cp.async.wait_group 1;");
        else
            asm volatile("cp.async.wait_group 0;");
        __syncthreads();

        const float* Kb = Ks + (it & 1) * 64 * QSTR;
        const float* Vb = Vs + (it & 1) * 64 * VSTR;

        // ---- S = Q @ K^T : paired LDS.64 loads (k-slot perm t->2t) ----
        float s[8][4];
#pragma unroll
        for (int nt = 0; nt < 8; nt++)
#pragma unroll
            for (int e = 0; e < 4; e++) s[nt][e] = 0.f;

#pragma unroll
        for (int kk = 0; kk < 64; kk += 8) {
            float2 qa = *(const float2*)&Qs[(mb + g) * QSTR + kk + 2 * t];
            float2 qb = *(const float2*)&Qs[(mb + g + 8) * QSTR + kk + 2 * t];
#pragma unroll
            for (int nt = 0; nt < 8; nt++) {
                float2 kv = *(const float2*)&Kb[(nt * 8 + g) * QSTR + kk + 2 * t];
                mma_tf32(s[nt], fu(qa.x), fu(qb.x), fu(qa.y), fu(qb.y),
                         fu(kv.x), fu(kv.y));
            }
        }

        // ---- P = ex2(S) (RNA tf32), warp-private rowsums ----
#pragma unroll
        for (int nt = 0; nt < 8; nt++) {
#pragma unroll
            for (int e = 0; e < 4; e++)
                s[nt][e] = uf(f2tf(ex2(s[nt][e])));
            l0 += s[nt][0] + s[nt][1];
            l1 += s[nt][2] + s[nt][3];
        }

        // ---- O += P @ V : S-frag as A (k-perm); scalar V loads, stride 68 ----
#pragma unroll
        for (int kc = 0; kc < 8; kc++) {
            uint32_t a0 = fu(s[kc][0]), a1 = fu(s[kc][2]);
            uint32_t a2 = fu(s[kc][1]), a3 = fu(s[kc][3]);
            const int kb = kc * 8;
#pragma unroll
            for (int nt = 0; nt < 8; nt++) {
                uint32_t b0 = fu(Vb[(kb + 2 * t) * VSTR + nt * 8 + g]);
                uint32_t b1 = fu(Vb[(kb + 2 * t + 1) * VSTR + nt * 8 + g]);
                mma_tf32(o[nt], a0, a1, a2, a3, b0, b1);
            }
        }
        __syncthreads();  // all warps done reading buffer (it&1)

        // ---- refill buffer (it&1) with tile it+2 ----
        if (it + 2 < NT) {
            const size_t cb = (size_t)(it + 2) * 64;
            const uint32_t kb_u = ks_u + (uint32_t)((it & 1) * 64 * QSTR) * 4;
            const uint32_t vb_u = vs_u + (uint32_t)((it & 1) * 64 * VSTR) * 4;
#pragma unroll
            for (int i = 0; i < 4; i++) {
                int rr = lr + i * 16;
                cp16(kb_u + (uint32_t)(rr * QSTR + lc * 4) * 4,
                     Kp + (cb + rr) * INNER + lc * 4);
                cp16(vb_u + (uint32_t)(rr * VSTR + lc * 4) * 4,
                     Vp + (cb + rr) * INNER + lc * 4);
            }
            asm volatile("cp.async.commit_group;");
        }
    }

    // ---- rowsum reduction (within quad) and writeout ----
    l0 += __shfl_xor_sync(0xffffffffu, l0, 1);
    l0 += __shfl_xor_sync(0xffffffffu, l0, 2);
    l1 += __shfl_xor_sync(0xffffffffu, l1, 1);
    l1 += __shfl_xor_sync(0xffffffffu, l1, 2);
    const float inv0 = 1.f / l0, inv1 = 1.f / l1;

    const size_t row = (size_t)b * NN + r0 + mb + g;
    float* op0 = g_O + row * INNER + h * DH;
    float* op1 = op0 + 8 * INNER;
#pragma unroll
    for (int nt = 0; nt < 8; nt++) {
        int c = nt * 8 + 2 * t;
        *(float2*)(op0 + c) = make_float2(o[nt][0] * inv0, o[nt][1] * inv0);
        *(float2*)(op1 + c) = make_float2(o[nt][2] * inv1, o[nt][3] * inv1);
    }
}

// ---------------------------------------------------------------------------
extern "C" void kernel_launch(void* const* d_in, const int* in_sizes, int n_in,
                              void* d_out, int out_size) {
    const float* x  = (const float*)d_in[0];
    const float* Wq = (const float*)d_in[1];
    const float* Wk = (const float*)d_in[2];
    const float* Wv = (const float*)d_in[3];
    const float* Wo = (const float*)d_in[4];
    const float* bo = (const float*)d_in[5];
    float* out = (float*)d_out;

    float *Qp, *Kp, *Vp, *Op;
    cudaGetSymbolAddress((void**)&Qp, g_Q);
    cudaGetSymbolAddress((void**)&Kp, g_K);
    cudaGetSymbolAddress((void**)&Vp, g_V);
    cudaGetSymbolAddress((void**)&Op, g_O);

    const int smem_gemm =
        (2 * (2 * 128 * ASTR) + 2 * (2 * 32 * BSTR)) * sizeof(float);  // 149504
    const int smem_attn =
        (128 * QSTR + 2 * 64 * QSTR + 2 * 64 * VSTR) * sizeof(float);  // 108544

    cudaFuncSetAttribute(gemm_qkv, cudaFuncAttributeMaxDynamicSharedMemorySize,
                         smem_gemm);
    cudaFuncSetAttribute(gemm_out, cudaFuncAttributeMaxDynamicSharedMemorySize,
                         smem_gemm);
    cudaFuncSetAttribute(attn_tc5, cudaFuncAttributeMaxDynamicSharedMemorySize,
                         smem_attn);

    gemm_qkv<<<dim3(12, ROWS / 128), 256, smem_gemm>>>(x, Wq, Wk, Wv, Qp, Kp, Vp);

    attn_tc5<<<dim3(NN / 128, HEADS, BB), 256, smem_attn>>>();

    gemm_out<<<dim3(4, ROWS / 128), 256, smem_gemm>>>(Op, Wo, bo, out);
}

// round 11
// speedup vs baseline: 1.0573x; 1.0573x over previous
#include <cuda_runtime.h>
#include <math.h>
#include <stdint.h>

#define BB     2
#define NN     4096
#define QDIM   512
#define HEADS  8
#define DH     64
#define INNER  512
#define ROWS   (BB * NN)          // 8192
// 64^-0.5 * log2(e): S computed in log2 domain, P = ex2(S)
#define SCALE_L2E  (0.125f * 1.4426950408889634f)

#define QSTR   72      // Qs/Ks row stride: conflict-free paired (LDS.64) k-loads
#define VSTR   68      // Vs row stride: conflict-free scalar column loads
#define NT     (NN / 64)

// Scratch (device globals: allocation-free per harness rules)
__device__ float g_Q[(size_t)ROWS * INNER];
__device__ float g_K[(size_t)ROWS * INNER];
__device__ float g_V[(size_t)ROWS * INNER];
__device__ float g_O[(size_t)ROWS * INNER];

// ---------------------------------------------------------------------------
// helpers
// ---------------------------------------------------------------------------
__device__ __forceinline__ uint32_t f2tf(float x) {
    uint32_t u;
    asm("cvt.rna.tf32.f32 %0, %1;" : "=r"(u) : "f"(x));
    return u;
}

__device__ __forceinline__ float ex2(float x) {
    float y;
    asm("ex2.approx.ftz.f32 %0, %1;" : "=f"(y) : "f"(x));
    return y;
}

__device__ __forceinline__ uint32_t fu(float x) { return __float_as_uint(x); }
__device__ __forceinline__ float uf(uint32_t x) { return __uint_as_float(x); }

__device__ __forceinline__ void mma_tf32(float d[4], uint32_t a0, uint32_t a1,
                                         uint32_t a2, uint32_t a3,
                                         uint32_t b0, uint32_t b1) {
    asm("mma.sync.aligned.m16n8k8.row.col.f32.tf32.tf32.f32 "
        "{%0,%1,%2,%3},{%4,%5,%6,%7},{%8,%9},{%0,%1,%2,%3};"
        : "+f"(d[0]), "+f"(d[1]), "+f"(d[2]), "+f"(d[3])
        : "r"(a0), "r"(a1), "r"(a2), "r"(a3), "r"(b0), "r"(b1));
}

__device__ __forceinline__ void split_tf(float x, uint32_t& hi, uint32_t& lo) {
    hi = f2tf(x);
    lo = f2tf(x - __uint_as_float(hi));
}

__device__ __forceinline__ void split4(float4 v, float4& h, float4& l) {
    uint32_t hx, lx, hy, ly, hz, lz, hw, lw;
    split_tf(v.x, hx, lx);
    split_tf(v.y, hy, ly);
    split_tf(v.z, hz, lz);
    split_tf(v.w, hw, lw);
    h = make_float4(uf(hx), uf(hy), uf(hz), uf(hw));
    l = make_float4(uf(lx), uf(ly), uf(lz), uf(lw));
}

__device__ __forceinline__ float4 rna4(float4 v) {
    return make_float4(uf(f2tf(v.x)), uf(f2tf(v.y)), uf(f2tf(v.z)), uf(f2tf(v.w)));
}

__device__ __forceinline__ void cp16(uint32_t dst, const void* src) {
    asm volatile("cp.async.cg.shared.global [%0], [%1], 16;" :: "r"(dst), "l"(src));
}

// ---------------------------------------------------------------------------
// GEMM 2xTF32 (A split hi/lo, B RNA-rounded): C = A[M,512] @ B[512,N] (+bias)
// Block 128x256, k-step 32, 512 threads / 16 warps (4m x 4n), warp tile 32x64.
// Register-staged double buffer (LDG -> split/rna -> STS).
// Per kk-step per warp: 8 LDS.64 + 16 scalar LDS feed 32 warp-mmas.
// ---------------------------------------------------------------------------
#define ASTR 40
#define BSTR 260
#define GN   512
#define GKT  16

__device__ __forceinline__ void ldg_tile2(const float* __restrict__ A,
                                          const float* __restrict__ Bm,
                                          int m0, int n0, int kt,
                                          float4 aR[2], float4 bR[4]) {
    const int tid = threadIdx.x;
#pragma unroll
    for (int i = 0; i < 2; i++) {
        int idx = tid + i * 512;
        int r = idx >> 3, c8 = idx & 7;
        aR[i] = *(const float4*)&A[(size_t)(m0 + r) * 512 + kt * 32 + c8 * 4];
    }
#pragma unroll
    for (int i = 0; i < 4; i++) {
        int idx = tid + i * 512;
        int r = idx >> 6, c4 = idx & 63;
        bR[i] = *(const float4*)&Bm[(size_t)(kt * 32 + r) * GN + n0 + c4 * 4];
    }
}

__device__ __forceinline__ void sts_tile2(float* Ahi, float* Alo, float* Bs,
                                          int buf,
                                          const float4 aR[2], const float4 bR[4]) {
    const int tid = threadIdx.x;
    float* ah = Ahi + buf * 128 * ASTR;
    float* al = Alo + buf * 128 * ASTR;
    float* bs = Bs + buf * 32 * BSTR;
#pragma unroll
    for (int i = 0; i < 2; i++) {
        int idx = tid + i * 512;
        int r = idx >> 3, c8 = idx & 7;
        float4 h, l;
        split4(aR[i], h, l);
        *(float4*)&ah[r * ASTR + c8 * 4] = h;
        *(float4*)&al[r * ASTR + c8 * 4] = l;
    }
#pragma unroll
    for (int i = 0; i < 4; i++) {
        int idx = tid + i * 512;
        int r = idx >> 6, c4 = idx & 63;
        *(float4*)&bs[r * BSTR + c4 * 4] = rna4(bR[i]);
    }
}

__device__ __forceinline__ void gemm2x_core(const float* __restrict__ A,
                                            const float* __restrict__ Bm,
                                            const float* __restrict__ bias,
                                            float* __restrict__ C,
                                            int m0, int n0, float* smg,
                                            bool has_bias) {
    float* Ahi = smg;                       // [2][128][ASTR]
    float* Alo = Ahi + 2 * 128 * ASTR;      // [2][128][ASTR]
    float* Bs  = Alo + 2 * 128 * ASTR;      // [2][32][BSTR]

    const int tid = threadIdx.x;
    const int lane = tid & 31, wid = tid >> 5;
    const int t = lane & 3, g = lane >> 2;
    const int wm = wid >> 2, wn = wid & 3;   // 4m x 4n warps

    float4 aR[2], bR[4];
    ldg_tile2(A, Bm, m0, n0, 0, aR, bR);
    sts_tile2(Ahi, Alo, Bs, 0, aR, bR);
    ldg_tile2(A, Bm, m0, n0, 1, aR, bR);
    __syncthreads();

    float acc[2][8][4];
#pragma unroll
    for (int i = 0; i < 2; i++)
#pragma unroll
        for (int j = 0; j < 8; j++)
#pragma unroll
            for (int e = 0; e < 4; e++) acc[i][j][e] = 0.f;

    for (int kt = 0; kt < GKT; kt++) {
        const float* ah = Ahi + (kt & 1) * 128 * ASTR;
        const float* al = Alo + (kt & 1) * 128 * ASTR;
        const float* bs = Bs + (kt & 1) * 32 * BSTR;

#pragma unroll
        for (int kk = 0; kk < 32; kk += 8) {
            uint32_t Ah[2][4], Al[2][4];
#pragma unroll
            for (int mt = 0; mt < 2; mt++) {
                int mb = wm * 32 + mt * 16;
                float2 h0 = *(const float2*)&ah[(mb + g) * ASTR + kk + 2 * t];
                float2 h1 = *(const float2*)&ah[(mb + g + 8) * ASTR + kk + 2 * t];
                float2 l0 = *(const float2*)&al[(mb + g) * ASTR + kk + 2 * t];
                float2 l1 = *(const float2*)&al[(mb + g + 8) * ASTR + kk + 2 * t];
                Ah[mt][0] = fu(h0.x); Ah[mt][1] = fu(h1.x);
                Ah[mt][2] = fu(h0.y); Ah[mt][3] = fu(h1.y);
                Al[mt][0] = fu(l0.x); Al[mt][1] = fu(l1.x);
                Al[mt][2] = fu(l0.y); Al[mt][3] = fu(l1.y);
            }
#pragma unroll
            for (int nt = 0; nt < 8; nt++) {
                int nb = wn * 64 + nt * 8;
                uint32_t b0 = fu(bs[(kk + 2 * t) * BSTR + nb + g]);
                uint32_t b1 = fu(bs[(kk + 2 * t + 1) * BSTR + nb + g]);
#pragma unroll
                for (int mt = 0; mt < 2; mt++) {
                    mma_tf32(acc[mt][nt], Ah[mt][0], Ah[mt][1], Ah[mt][2], Ah[mt][3],
                             b0, b1);
                    mma_tf32(acc[mt][nt], Al[mt][0], Al[mt][1], Al[mt][2], Al[mt][3],
                             b0, b1);
                }
            }
        }

        if (kt + 1 < GKT) {
            __syncthreads();   // slowest warp done reading buf (kt+1)&1 (from kt-1)
            sts_tile2(Ahi, Alo, Bs, (kt + 1) & 1, aR, bR);
            __syncthreads();   // tile kt+1 visible
            if (kt + 2 < GKT) ldg_tile2(A, Bm, m0, n0, kt + 2, aR, bR);
        }
    }

    // epilogue
#pragma unroll
    for (int mt = 0; mt < 2; mt++) {
#pragma unroll
        for (int nt = 0; nt < 8; nt++) {
            int r = m0 + wm * 32 + mt * 16 + g;
            int c = n0 + wn * 64 + nt * 8 + 2 * t;
            float b0 = has_bias ? bias[c] : 0.f;
            float b1 = has_bias ? bias[c + 1] : 0.f;
            float2 v0 = make_float2(acc[mt][nt][0] + b0, acc[mt][nt][1] + b1);
            float2 v1 = make_float2(acc[mt][nt][2] + b0, acc[mt][nt][3] + b1);
            *(float2*)&C[(size_t)r * GN + c] = v0;
            *(float2*)&C[(size_t)(r + 8) * GN + c] = v1;
        }
    }
}

// Fused QKV projection: grid.x = 6 (3 matrices x 2 n-blocks of 256)
__global__ __launch_bounds__(512, 1) void gemm_qkv(const float* __restrict__ x,
                                                   const float* __restrict__ Wq,
                                                   const float* __restrict__ Wk,
                                                   const float* __restrict__ Wv,
                                                   float* __restrict__ Qd,
                                                   float* __restrict__ Kd,
                                                   float* __restrict__ Vd) {
    extern __shared__ float smg[];
    const int sel = blockIdx.x >> 1;
    const float* B = (sel == 0) ? Wq : (sel == 1) ? Wk : Wv;
    float* C = (sel == 0) ? Qd : (sel == 1) ? Kd : Vd;
    gemm2x_core(x, B, nullptr, C, blockIdx.y * 128, (blockIdx.x & 1) * 256, smg,
                false);
}

// Output projection (with bias): grid.x = 2
__global__ __launch_bounds__(512, 1) void gemm_out(const float* __restrict__ A,
                                                   const float* __restrict__ Wo,
                                                   const float* __restrict__ bo,
                                                   float* __restrict__ out) {
    extern __shared__ float smg[];
    gemm2x_core(A, Wo, bo, out, blockIdx.y * 128, blockIdx.x * 256, smg, true);
}

// ---------------------------------------------------------------------------
// Flash attention v5 (unchanged, 760us-baseline): warp-row ownership;
// K+V double-buffered cp.async (depth 2); LDS.64 S-phase fragment loads
// (k-slot perm, stride 72); conflict-free scalar PV loads (stride 68).
// 2 CTAs/SM. Softmax in log2 domain (ex2), no max-subtraction.
// ---------------------------------------------------------------------------
__global__ __launch_bounds__(256, 2) void attn_tc5() {
    extern __shared__ float sm[];
    float* Qs = sm;                                   // [128][QSTR]
    float* Ks = sm + 128 * QSTR;                      // [2][64][QSTR]
    float* Vs = sm + 128 * QSTR + 2 * 64 * QSTR;      // [2][64][VSTR]

    const int tid = threadIdx.x;
    const int lane = tid & 31, wid = tid >> 5;
    const int t = lane & 3, g = lane >> 2;
    const int b = blockIdx.z, h = blockIdx.y;
    const int r0 = blockIdx.x * 128;
    const int mb = wid * 16;

    const float* Qp = g_Q + ((size_t)b * NN + r0) * INNER + h * DH;
    const float* Kp = g_K + ((size_t)b * NN) * INNER + h * DH;
    const float* Vp = g_V + ((size_t)b * NN) * INNER + h * DH;

    const uint32_t ks_u = (uint32_t)__cvta_generic_to_shared(Ks);
    const uint32_t vs_u = (uint32_t)__cvta_generic_to_shared(Vs);
    const int lr = tid >> 4, lc = tid & 15;

    // --- pre-issue KV tiles 0,1 (one commit group per tile) ---
#pragma unroll
    for (int pre = 0; pre < 2; pre++) {
#pragma unroll
        for (int i = 0; i < 4; i++) {
            int rr = lr + i * 16;
            cp16(ks_u + (uint32_t)(pre * 64 * QSTR + rr * QSTR + lc * 4) * 4,
                 Kp + (size_t)(pre * 64 + rr) * INNER + lc * 4);
            cp16(vs_u + (uint32_t)(pre * 64 * VSTR + rr * VSTR + lc * 4) * 4,
                 Vp + (size_t)(pre * 64 + rr) * INNER + lc * 4);
        }
        asm volatile("cp.async.commit_group;");
    }

    // --- stage Q (fold scale*log2e, single RNA tf32 round) ---
#pragma unroll
    for (int i = 0; i < 8; i++) {
        int idx = tid + i * 256;
        int r = idx >> 4, c4 = idx & 15;
        float4 v = *(const float4*)&Qp[(size_t)r * INNER + c4 * 4];
        float4 w;
        w.x = uf(f2tf(v.x * SCALE_L2E));
        w.y = uf(f2tf(v.y * SCALE_L2E));
        w.z = uf(f2tf(v.z * SCALE_L2E));
        w.w = uf(f2tf(v.w * SCALE_L2E));
        *(float4*)&Qs[r * QSTR + c4 * 4] = w;
    }

    float o[8][4];
#pragma unroll
    for (int nt = 0; nt < 8; nt++)
#pragma unroll
        for (int e = 0; e < 4; e++) o[nt][e] = 0.f;
    float l0 = 0.f, l1 = 0.f;

    for (int it = 0; it < NT; ++it) {
        if (it + 1 < NT)
            asm volatile("cp.async.wait_group 1;");
        else
            asm volatile("cp.async.wait_group 0;");
        __syncthreads();

        const float* Kb = Ks + (it & 1) * 64 * QSTR;
        const float* Vb = Vs + (it & 1) * 64 * VSTR;

        // ---- S = Q @ K^T : paired LDS.64 loads (k-slot perm t->2t) ----
        float s[8][4];
#pragma unroll
        for (int nt = 0; nt < 8; nt++)
#pragma unroll
            for (int e = 0; e < 4; e++) s[nt][e] = 0.f;

#pragma unroll
        for (int kk = 0; kk < 64; kk += 8) {
            float2 qa = *(const float2*)&Qs[(mb + g) * QSTR + kk + 2 * t];
            float2 qb = *(const float2*)&Qs[(mb + g + 8) * QSTR + kk + 2 * t];
#pragma unroll
            for (int nt = 0; nt < 8; nt++) {
                float2 kv = *(const float2*)&Kb[(nt * 8 + g) * QSTR + kk + 2 * t];
                mma_tf32(s[nt], fu(qa.x), fu(qb.x), fu(qa.y), fu(qb.y),
                         fu(kv.x), fu(kv.y));
            }
        }

        // ---- P = ex2(S) (RNA tf32), warp-private rowsums ----
#pragma unroll
        for (int nt = 0; nt < 8; nt++) {
#pragma unroll
            for (int e = 0; e < 4; e++)
                s[nt][e] = uf(f2tf(ex2(s[nt][e])));
            l0 += s[nt][0] + s[nt][1];
            l1 += s[nt][2] + s[nt][3];
        }

        // ---- O += P @ V : S-frag as A (k-perm); scalar V loads, stride 68 ----
#pragma unroll
        for (int kc = 0; kc < 8; kc++) {
            uint32_t a0 = fu(s[kc][0]), a1 = fu(s[kc][2]);
            uint32_t a2 = fu(s[kc][1]), a3 = fu(s[kc][3]);
            const int kb = kc * 8;
#pragma unroll
            for (int nt = 0; nt < 8; nt++) {
                uint32_t b0 = fu(Vb[(kb + 2 * t) * VSTR + nt * 8 + g]);
                uint32_t b1 = fu(Vb[(kb + 2 * t + 1) * VSTR + nt * 8 + g]);
                mma_tf32(o[nt], a0, a1, a2, a3, b0, b1);
            }
        }
        __syncthreads();  // all warps done reading buffer (it&1)

        // ---- refill buffer (it&1) with tile it+2 ----
        if (it + 2 < NT) {
            const size_t cb = (size_t)(it + 2) * 64;
            const uint32_t kb_u = ks_u + (uint32_t)((it & 1) * 64 * QSTR) * 4;
            const uint32_t vb_u = vs_u + (uint32_t)((it & 1) * 64 * VSTR) * 4;
#pragma unroll
            for (int i = 0; i < 4; i++) {
                int rr = lr + i * 16;
                cp16(kb_u + (uint32_t)(rr * QSTR + lc * 4) * 4,
                     Kp + (cb + rr) * INNER + lc * 4);
                cp16(vb_u + (uint32_t)(rr * VSTR + lc * 4) * 4,
                     Vp + (cb + rr) * INNER + lc * 4);
            }
            asm volatile("cp.async.commit_group;");
        }
    }

    // ---- rowsum reduction (within quad) and writeout ----
    l0 += __shfl_xor_sync(0xffffffffu, l0, 1);
    l0 += __shfl_xor_sync(0xffffffffu, l0, 2);
    l1 += __shfl_xor_sync(0xffffffffu, l1, 1);
    l1 += __shfl_xor_sync(0xffffffffu, l1, 2);
    const float inv0 = 1.f / l0, inv1 = 1.f / l1;

    const size_t row = (size_t)b * NN + r0 + mb + g;
    float* op0 = g_O + row * INNER + h * DH;
    float* op1 = op0 + 8 * INNER;
#pragma unroll
    for (int nt = 0; nt < 8; nt++) {
        int c = nt * 8 + 2 * t;
        *(float2*)(op0 + c) = make_float2(o[nt][0] * inv0, o[nt][1] * inv0);
        *(float2*)(op1 + c) = make_float2(o[nt][2] * inv1, o[nt][3] * inv1);
    }
}

// ---------------------------------------------------------------------------
extern "C" void kernel_launch(void* const* d_in, const int* in_sizes, int n_in,
                              void* d_out, int out_size) {
    const float* x  = (const float*)d_in[0];
    const float* Wq = (const float*)d_in[1];
    const float* Wk = (const float*)d_in[2];
    const float* Wv = (const float*)d_in[3];
    const float* Wo = (const float*)d_in[4];
    const float* bo = (const float*)d_in[5];
    float* out = (float*)d_out;

    float *Qp, *Kp, *Vp, *Op;
    cudaGetSymbolAddress((void**)&Qp, g_Q);
    cudaGetSymbolAddress((void**)&Kp, g_K);
    cudaGetSymbolAddress((void**)&Vp, g_V);
    cudaGetSymbolAddress((void**)&Op, g_O);

    const int smem_gemm =
        (2 * (2 * 128 * ASTR) + 2 * 32 * BSTR) * sizeof(float);        // 148480
    const int smem_attn =
        (128 * QSTR + 2 * 64 * QSTR + 2 * 64 * VSTR) * sizeof(float);  // 108544

    cudaFuncSetAttribute(gemm_qkv, cudaFuncAttributeMaxDynamicSharedMemorySize,
                         smem_gemm);
    cudaFuncSetAttribute(gemm_out, cudaFuncAttributeMaxDynamicSharedMemorySize,
                         smem_gemm);
    cudaFuncSetAttribute(attn_tc5, cudaFuncAttributeMaxDynamicSharedMemorySize,
                         smem_attn);

    gemm_qkv<<<dim3(6, ROWS / 128), 512, smem_gemm>>>(x, Wq, Wk, Wv, Qp, Kp, Vp);

    attn_tc5<<<dim3(NN / 128, HEADS, BB), 256, smem_attn>>>();

    gemm_out<<<dim3(2, ROWS / 128), 512, smem_gemm>>>(Op, Wo, bo, out);
}

// round 12
// speedup vs baseline: 1.1657x; 1.1025x over previous
#include <cuda_runtime.h>
#include <math.h>
#include <stdint.h>

#define BB     2
#define NN     4096
#define QDIM   512
#define HEADS  8
#define DH     64
#define INNER  512
#define ROWS   (BB * NN)          // 8192
// 64^-0.5 * log2(e): S computed in log2 domain, P = ex2(S)
#define SCALE_L2E  (0.125f * 1.4426950408889634f)

#define QSTR   72      // Ks row stride: conflict-free paired (LDS.64) k-loads
#define VSTR   68      // Vs row stride: conflict-free scalar column loads
#define NT     (NN / 64)
#define WN     (512 * 512)

// Scratch (device globals: allocation-free per harness rules)
__device__ float g_Q[(size_t)ROWS * INNER];
__device__ float g_K[(size_t)ROWS * INNER];
__device__ float g_V[(size_t)ROWS * INNER];
__device__ float g_OH[(size_t)ROWS * INNER];   // attention output, hi part
__device__ float g_OL[(size_t)ROWS * INNER];   // attention output, lo part
__device__ float g_XH[(size_t)ROWS * QDIM];    // x split hi
__device__ float g_XL[(size_t)ROWS * QDIM];    // x split lo
__device__ float g_WR[(size_t)4 * WN];         // Wq,Wk,Wv,Wo RNA-rounded

// ---------------------------------------------------------------------------
// helpers
// ---------------------------------------------------------------------------
__device__ __forceinline__ uint32_t f2tf(float x) {
    uint32_t u;
    asm("cvt.rna.tf32.f32 %0, %1;" : "=r"(u) : "f"(x));
    return u;
}

__device__ __forceinline__ float ex2(float x) {
    float y;
    asm("ex2.approx.ftz.f32 %0, %1;" : "=f"(y) : "f"(x));
    return y;
}

__device__ __forceinline__ uint32_t fu(float x) { return __float_as_uint(x); }
__device__ __forceinline__ float uf(uint32_t x) { return __uint_as_float(x); }

__device__ __forceinline__ void mma_tf32(float d[4], uint32_t a0, uint32_t a1,
                                         uint32_t a2, uint32_t a3,
                                         uint32_t b0, uint32_t b1) {
    asm("mma.sync.aligned.m16n8k8.row.col.f32.tf32.tf32.f32 "
        "{%0,%1,%2,%3},{%4,%5,%6,%7},{%8,%9},{%0,%1,%2,%3};"
        : "+f"(d[0]), "+f"(d[1]), "+f"(d[2]), "+f"(d[3])
        : "r"(a0), "r"(a1), "r"(a2), "r"(a3), "r"(b0), "r"(b1));
}

__device__ __forceinline__ void split_tf(float x, uint32_t& hi, uint32_t& lo) {
    hi = f2tf(x);
    lo = f2tf(x - __uint_as_float(hi));
}

__device__ __forceinline__ void split4(float4 v, float4& h, float4& l) {
    uint32_t hx, lx, hy, ly, hz, lz, hw, lw;
    split_tf(v.x, hx, lx);
    split_tf(v.y, hy, ly);
    split_tf(v.z, hz, lz);
    split_tf(v.w, hw, lw);
    h = make_float4(uf(hx), uf(hy), uf(hz), uf(hw));
    l = make_float4(uf(lx), uf(ly), uf(lz), uf(lw));
}

__device__ __forceinline__ float4 rna4(float4 v) {
    return make_float4(uf(f2tf(v.x)), uf(f2tf(v.y)), uf(f2tf(v.z)), uf(f2tf(v.w)));
}

__device__ __forceinline__ void cp16(uint32_t dst, const void* src) {
    asm volatile("cp.async.cg.shared.global [%0], [%1], 16;" :: "r"(dst), "l"(src));
}

// ---------------------------------------------------------------------------
// Prep: split x -> (XH, XL); RNA-round Wq/Wk/Wv/Wo -> g_WR. One-time, ~10us.
// ---------------------------------------------------------------------------
#define NX4 (ROWS * QDIM / 4)        // 1048576 float4
#define NW4 (4 * WN / 4)             // 262144 float4

__global__ __launch_bounds__(256) void prep_kernel(const float* __restrict__ x,
                                                   const float* __restrict__ Wq,
                                                   const float* __restrict__ Wk,
                                                   const float* __restrict__ Wv,
                                                   const float* __restrict__ Wo) {
    int gid = blockIdx.x * 256 + threadIdx.x;
    if (gid < NX4) {
        float4 v = ((const float4*)x)[gid];
        float4 h, l;
        split4(v, h, l);
        ((float4*)g_XH)[gid] = h;
        ((float4*)g_XL)[gid] = l;
    } else if (gid < NX4 + NW4) {
        int g2 = gid - NX4;
        int w = g2 >> 16, off = g2 & 65535;
        const float* src = (w == 0) ? Wq : (w == 1) ? Wk : (w == 2) ? Wv : Wo;
        float4 v = ((const float4*)src)[off];
        ((float4*)(g_WR + (size_t)w * WN))[off] = rna4(v);
    }
}

// ---------------------------------------------------------------------------
// GEMM 2xTF32, all-cp.async, triple-buffered, ONE sync per k-tile.
// C[.,512] = (Ah+Al)[M,512] @ Bw[512,512] (+bias). Block 128x256, k-step 32,
// 512 threads / 16 warps (4m x 4n), warp tile 32x64.
// ---------------------------------------------------------------------------
#define ASTR 40
#define BSTR 260
#define GN   512
#define GKT  16

__device__ __forceinline__ void gemm_issue(const float* __restrict__ Ah,
                                           const float* __restrict__ Al,
                                           const float* __restrict__ Bw,
                                           int m0, int n0, int kt, int ib,
                                           uint32_t ah_u, uint32_t al_u,
                                           uint32_t bs_u) {
    const int tid = threadIdx.x;
#pragma unroll
    for (int i = 0; i < 2; i++) {
        int idx = tid + i * 512;
        int r = idx >> 3, c8 = idx & 7;
        uint32_t off = (uint32_t)(ib * 128 * ASTR + r * ASTR + c8 * 4) * 4;
        size_t goff = (size_t)(m0 + r) * 512 + kt * 32 + c8 * 4;
        cp16(ah_u + off, Ah + goff);
        cp16(al_u + off, Al + goff);
    }
#pragma unroll
    for (int i = 0; i < 4; i++) {
        int idx = tid + i * 512;
        int r = idx >> 6, c4 = idx & 63;
        cp16(bs_u + (uint32_t)(ib * 32 * BSTR + r * BSTR + c4 * 4) * 4,
             Bw + (size_t)(kt * 32 + r) * GN + n0 + c4 * 4);
    }
    asm volatile("cp.async.commit_group;");
}

__device__ __forceinline__ void gemm2x_core(const float* __restrict__ Ah,
                                            const float* __restrict__ Al,
                                            const float* __restrict__ Bw,
                                            const float* __restrict__ bias,
                                            float* __restrict__ C,
                                            int m0, int n0, float* smg,
                                            bool has_bias) {
    float* Ahs = smg;                        // [3][128][ASTR]
    float* Als = Ahs + 3 * 128 * ASTR;       // [3][128][ASTR]
    float* Bs  = Als + 3 * 128 * ASTR;       // [3][32][BSTR]

    const int tid = threadIdx.x;
    const int lane = tid & 31, wid = tid >> 5;
    const int t = lane & 3, g = lane >> 2;
    const int wm = wid >> 2, wn = wid & 3;   // 4m x 4n warps

    const uint32_t ah_u = (uint32_t)__cvta_generic_to_shared(Ahs);
    const uint32_t al_u = (uint32_t)__cvta_generic_to_shared(Als);
    const uint32_t bs_u = (uint32_t)__cvta_generic_to_shared(Bs);

    gemm_issue(Ah, Al, Bw, m0, n0, 0, 0, ah_u, al_u, bs_u);
    gemm_issue(Ah, Al, Bw, m0, n0, 1, 1, ah_u, al_u, bs_u);

    float acc[2][8][4];
#pragma unroll
    for (int i = 0; i < 2; i++)
#pragma unroll
        for (int j = 0; j < 8; j++)
#pragma unroll
            for (int e = 0; e < 4; e++) acc[i][j][e] = 0.f;

    int cur = 0;
    for (int kt = 0; kt < GKT; kt++) {
        if (kt + 1 < GKT)
            asm volatile("cp.async.wait_group 1;");
        else
            asm volatile("cp.async.wait_group 0;");
        __syncthreads();   // tile kt visible; all warps done with tile kt-1

        if (kt + 2 < GKT) {
            int ib = cur + 2;
            if (ib >= 3) ib -= 3;
            gemm_issue(Ah, Al, Bw, m0, n0, kt + 2, ib, ah_u, al_u, bs_u);
        }

        const float* ah = Ahs + cur * 128 * ASTR;
        const float* al = Als + cur * 128 * ASTR;
        const float* bs = Bs + cur * 32 * BSTR;

#pragma unroll
        for (int kk = 0; kk < 32; kk += 8) {
            uint32_t Am[2][4], Al2[2][4];
#pragma unroll
            for (int mt = 0; mt < 2; mt++) {
                int mb = wm * 32 + mt * 16;
                float2 h0 = *(const float2*)&ah[(mb + g) * ASTR + kk + 2 * t];
                float2 h1 = *(const float2*)&ah[(mb + g + 8) * ASTR + kk + 2 * t];
                float2 l0 = *(const float2*)&al[(mb + g) * ASTR + kk + 2 * t];
                float2 l1 = *(const float2*)&al[(mb + g + 8) * ASTR + kk + 2 * t];
                Am[mt][0] = fu(h0.x); Am[mt][1] = fu(h1.x);
                Am[mt][2] = fu(h0.y); Am[mt][3] = fu(h1.y);
                Al2[mt][0] = fu(l0.x); Al2[mt][1] = fu(l1.x);
                Al2[mt][2] = fu(l0.y); Al2[mt][3] = fu(l1.y);
            }
#pragma unroll
            for (int nt = 0; nt < 8; nt++) {
                int nb = wn * 64 + nt * 8;
                uint32_t b0 = fu(bs[(kk + 2 * t) * BSTR + nb + g]);
                uint32_t b1 = fu(bs[(kk + 2 * t + 1) * BSTR + nb + g]);
#pragma unroll
                for (int mt = 0; mt < 2; mt++) {
                    mma_tf32(acc[mt][nt], Am[mt][0], Am[mt][1], Am[mt][2], Am[mt][3],
                             b0, b1);
                    mma_tf32(acc[mt][nt], Al2[mt][0], Al2[mt][1], Al2[mt][2],
                             Al2[mt][3], b0, b1);
                }
            }
        }
        cur = (cur == 2) ? 0 : cur + 1;
    }

    // epilogue
#pragma unroll
    for (int mt = 0; mt < 2; mt++) {
#pragma unroll
        for (int nt = 0; nt < 8; nt++) {
            int r = m0 + wm * 32 + mt * 16 + g;
            int c = n0 + wn * 64 + nt * 8 + 2 * t;
            float b0 = has_bias ? bias[c] : 0.f;
            float b1 = has_bias ? bias[c + 1] : 0.f;
            float2 v0 = make_float2(acc[mt][nt][0] + b0, acc[mt][nt][1] + b1);
            float2 v1 = make_float2(acc[mt][nt][2] + b0, acc[mt][nt][3] + b1);
            *(float2*)&C[(size_t)r * GN + c] = v0;
            *(float2*)&C[(size_t)(r + 8) * GN + c] = v1;
        }
    }
}

// Fused QKV projection: grid.x = 6 (3 matrices x 2 n-blocks of 256)
__global__ __launch_bounds__(512, 1) void gemm_qkv(float* __restrict__ Qd,
                                                   float* __restrict__ Kd,
                                                   float* __restrict__ Vd) {
    extern __shared__ float smg[];
    const int sel = blockIdx.x >> 1;
    const float* Bw = g_WR + (size_t)sel * WN;
    float* C = (sel == 0) ? Qd : (sel == 1) ? Kd : Vd;
    gemm2x_core(g_XH, g_XL, Bw, nullptr, C, blockIdx.y * 128,
                (blockIdx.x & 1) * 256, smg, false);
}

// Output projection (with bias): grid.x = 2
__global__ __launch_bounds__(512, 1) void gemm_out(const float* __restrict__ bo,
                                                   float* __restrict__ out) {
    extern __shared__ float smg[];
    gemm2x_core(g_OH, g_OL, g_WR + (size_t)3 * WN, bo, out, blockIdx.y * 128,
                blockIdx.x * 256, smg, true);
}

// ---------------------------------------------------------------------------
// Flash attention v6: Q fragments in registers; K+V triple-buffered cp.async;
// ONE __syncthreads per KV tile; LDS.64 S-phase K loads (k-slot perm, stride
// 72); conflict-free scalar PV loads (stride 68). 2 CTAs/SM.
// Softmax in log2 domain (ex2), no max-subtraction (logits bounded).
// Writes O split (hi/lo) for the 2xTF32 output projection.
// ---------------------------------------------------------------------------
__device__ __forceinline__ void attn_issue(const float* __restrict__ Kp,
                                           const float* __restrict__ Vp,
                                           int tile, int ib, uint32_t ks_u,
                                           uint32_t vs_u, int lr, int lc) {
    const size_t cb = (size_t)tile * 64;
#pragma unroll
    for (int i = 0; i < 4; i++) {
        int rr = lr + i * 16;
        cp16(ks_u + (uint32_t)(ib * 64 * QSTR + rr * QSTR + lc * 4) * 4,
             Kp + (cb + rr) * INNER + lc * 4);
        cp16(vs_u + (uint32_t)(ib * 64 * VSTR + rr * VSTR + lc * 4) * 4,
             Vp + (cb + rr) * INNER + lc * 4);
    }
    asm volatile("cp.async.commit_group;");
}

__global__ __launch_bounds__(256, 2) void attn_tc6() {
    extern __shared__ float sm[];
    float* Ks = sm;                     // [3][64][QSTR]
    float* Vs = sm + 3 * 64 * QSTR;     // [3][64][VSTR]

    const int tid = threadIdx.x;
    const int lane = tid & 31, wid = tid >> 5;
    const int t = lane & 3, g = lane >> 2;
    const int b = blockIdx.z, h = blockIdx.y;
    const int r0 = blockIdx.x * 128;
    const int mb = wid * 16;

    const float* Kp = g_K + ((size_t)b * NN) * INNER + h * DH;
    const float* Vp = g_V + ((size_t)b * NN) * INNER + h * DH;

    const uint32_t ks_u = (uint32_t)__cvta_generic_to_shared(Ks);
    const uint32_t vs_u = (uint32_t)__cvta_generic_to_shared(Vs);
    const int lr = tid >> 4, lc = tid & 15;

    // --- pre-issue KV tiles 0,1 into bufs 0,1 ---
    attn_issue(Kp, Vp, 0, 0, ks_u, vs_u, lr, lc);
    attn_issue(Kp, Vp, 1, 1, ks_u, vs_u, lr, lc);

    // --- Q fragments in registers (each warp owns its 16 rows) ---
    float2 qa[8], qb[8];
    {
        const size_t row = (size_t)b * NN + r0 + mb + g;
        const float* q0 = g_Q + row * INNER + h * DH;
        const float* q1 = q0 + 8 * INNER;
#pragma unroll
        for (int k8 = 0; k8 < 8; k8++) {
            float2 v0 = *(const float2*)&q0[k8 * 8 + 2 * t];
            float2 v1 = *(const float2*)&q1[k8 * 8 + 2 * t];
            qa[k8] = make_float2(uf(f2tf(v0.x * SCALE_L2E)),
                                 uf(f2tf(v0.y * SCALE_L2E)));
            qb[k8] = make_float2(uf(f2tf(v1.x * SCALE_L2E)),
                                 uf(f2tf(v1.y * SCALE_L2E)));
        }
    }

    float o[8][4];
#pragma unroll
    for (int nt = 0; nt < 8; nt++)
#pragma unroll
        for (int e = 0; e < 4; e++) o[nt][e] = 0.f;
    float l0 = 0.f, l1 = 0.f;

    int cur = 0;
    for (int it = 0; it < NT; ++it) {
        if (it + 1 < NT)
            asm volatile("cp.async.wait_group 1;");
        else
            asm volatile("cp.async.wait_group 0;");
        __syncthreads();   // tile it visible; all warps done with tile it-1

        // issue tile it+2 into the buffer tile it-1 occupied
        if (it + 2 < NT) {
            int ib = cur + 2;
            if (ib >= 3) ib -= 3;
            attn_issue(Kp, Vp, it + 2, ib, ks_u, vs_u, lr, lc);
        }

        const float* Kb = Ks + cur * 64 * QSTR;
        const float* Vb = Vs + cur * 64 * VSTR;

        // ---- S = Q @ K^T : K pair loads LDS.64 (k-slot perm t->2t) ----
        float s[8][4];
#pragma unroll
        for (int nt = 0; nt < 8; nt++)
#pragma unroll
            for (int e = 0; e < 4; e++) s[nt][e] = 0.f;

#pragma unroll
        for (int k8 = 0; k8 < 8; k8++) {
            uint32_t a0 = fu(qa[k8].x), a1 = fu(qb[k8].x);
            uint32_t a2 = fu(qa[k8].y), a3 = fu(qb[k8].y);
#pragma unroll
            for (int nt = 0; nt < 8; nt++) {
                float2 kv = *(const float2*)&Kb[(nt * 8 + g) * QSTR + k8 * 8 + 2 * t];
                mma_tf32(s[nt], a0, a1, a2, a3, fu(kv.x), fu(kv.y));
            }
        }

        // ---- P = ex2(S) (RNA tf32; consistent with rowsums), rowsums ----
#pragma unroll
        for (int nt = 0; nt < 8; nt++) {
#pragma unroll
            for (int e = 0; e < 4; e++)
                s[nt][e] = uf(f2tf(ex2(s[nt][e])));
            l0 += s[nt][0] + s[nt][1];
            l1 += s[nt][2] + s[nt][3];
        }

        // ---- O += P @ V : S-frag as A (k-perm); scalar V loads, stride 68 ----
#pragma unroll
        for (int kc = 0; kc < 8; kc++) {
            uint32_t a0 = fu(s[kc][0]), a1 = fu(s[kc][2]);
            uint32_t a2 = fu(s[kc][1]), a3 = fu(s[kc][3]);
            const int kb = kc * 8;
#pragma unroll
            for (int nt = 0; nt < 8; nt++) {
                uint32_t b0 = fu(Vb[(kb + 2 * t) * VSTR + nt * 8 + g]);
                uint32_t b1 = fu(Vb[(kb + 2 * t + 1) * VSTR + nt * 8 + g]);
                mma_tf32(o[nt], a0, a1, a2, a3, b0, b1);
            }
        }
        cur = (cur == 2) ? 0 : cur + 1;
    }

    // ---- rowsum reduction (within quad) and split writeout ----
    l0 += __shfl_xor_sync(0xffffffffu, l0, 1);
    l0 += __shfl_xor_sync(0xffffffffu, l0, 2);
    l1 += __shfl_xor_sync(0xffffffffu, l1, 1);
    l1 += __shfl_xor_sync(0xffffffffu, l1, 2);
    const float inv0 = 1.f / l0, inv1 = 1.f / l1;

    const size_t row = (size_t)b * NN + r0 + mb + g;
    const size_t base0 = row * INNER + h * DH;
    const size_t base1 = base0 + 8 * INNER;
#pragma unroll
    for (int nt = 0; nt < 8; nt++) {
        int c = nt * 8 + 2 * t;
        float v00 = o[nt][0] * inv0, v01 = o[nt][1] * inv0;
        float v10 = o[nt][2] * inv1, v11 = o[nt][3] * inv1;
        uint32_t h00, l00, h01, l01, h10, l10, h11, l11;
        split_tf(v00, h00, l00);
        split_tf(v01, h01, l01);
        split_tf(v10, h10, l10);
        split_tf(v11, h11, l11);
        *(float2*)&g_OH[base0 + c] = make_float2(uf(h00), uf(h01));
        *(float2*)&g_OL[base0 + c] = make_float2(uf(l00), uf(l01));
        *(float2*)&g_OH[base1 + c] = make_float2(uf(h10), uf(h11));
        *(float2*)&g_OL[base1 + c] = make_float2(uf(l10), uf(l11));
    }
}

// ---------------------------------------------------------------------------
extern "C" void kernel_launch(void* const* d_in, const int* in_sizes, int n_in,
                              void* d_out, int out_size) {
    const float* x  = (const float*)d_in[0];
    const float* Wq = (const float*)d_in[1];
    const float* Wk = (const float*)d_in[2];
    const float* Wv = (const float*)d_in[3];
    const float* Wo = (const float*)d_in[4];
    const float* bo = (const float*)d_in[5];
    float* out = (float*)d_out;

    float *Qp, *Kp, *Vp;
    cudaGetSymbolAddress((void**)&Qp, g_Q);
    cudaGetSymbolAddress((void**)&Kp, g_K);
    cudaGetSymbolAddress((void**)&Vp, g_V);

    const int smem_gemm =
        (3 * (2 * 128 * ASTR) + 3 * 32 * BSTR) * sizeof(float);   // 217愈? -> 222720 B
    const int smem_attn = (3 * 64 * (QSTR + VSTR)) * sizeof(float);  // 107520 B

    cudaFuncSetAttribute(gemm_qkv, cudaFuncAttributeMaxDynamicSharedMemorySize,
                         smem_gemm);
    cudaFuncSetAttribute(gemm_out, cudaFuncAttributeMaxDynamicSharedMemorySize,
                         smem_gemm);
    cudaFuncSetAttribute(attn_tc6, cudaFuncAttributeMaxDynamicSharedMemorySize,
                         smem_attn);

    prep_kernel<<<(NX4 + NW4 + 255) / 256, 256>>>(x, Wq, Wk, Wv, Wo);

    gemm_qkv<<<dim3(6, ROWS / 128), 512, smem_gemm>>>(Qp, Kp, Vp);

    attn_tc6<<<dim3(NN / 128, HEADS, BB), 256, smem_attn>>>();

    gemm_out<<<dim3(2, ROWS / 128), 512, smem_gemm>>>(bo, out);
}